// round 5
// baseline (speedup 1.0000x reference)
#include <cuda_runtime.h>
#include <cuda_bf16.h>

#define NM    16
#define HDIM  224
#define WDIM  224
#define CDIM  64
#define HW    (HDIM * WDIM)

// CTA = 32x16 strip (2 horizontal patches), 512 threads.
// thread = (pixel-quad g in strip 0..127, channel-slice 0..3).
// Warp-loads are 4 rows x 128B = 4 FULL cache lines, single-CTA consumption.
__global__ __launch_bounds__(512, 3)
void msp_dct_kernel(const float* __restrict__ x,
                    const float* __restrict__ bases,
                    float* __restrict__ out) {
    __shared__ float4 sPart[512];          // 8 KB partial channel sums
    __shared__ float  sW[4][2][NM];        // per-warp, per-patch partials
    __shared__ float  sCoef[2 * NM];       // final coefficients

    const int t   = threadIdx.x;
    const int w0  = blockIdx.x * 32;       // strip left edge
    const int h0  = blockIdx.y * 16;
    const int b   = blockIdx.z;

    const int g    = t & 127;              // quad index in strip
    const int row  = g >> 3;               // 0..15
    const int colq = g & 7;                // 0..7  (col = colq*4)
    const int csl  = t >> 7;               // channel slice 0..3

    // ---- phase 1: sum 16 channels, full-line warp loads ----
    {
        const float* p = x + ((size_t)(b * CDIM + csl * 16)) * HW
                           + (size_t)(h0 + row) * WDIM + (w0 + colq * 4);
        float4 acc = make_float4(0.f, 0.f, 0.f, 0.f);
        #pragma unroll
        for (int cc = 0; cc < 16; cc++) {
            const float4 v = __ldcs(reinterpret_cast<const float4*>(p + (size_t)cc * HW));
            acc.x += v.x; acc.y += v.y; acc.z += v.z; acc.w += v.w;
        }
        sPart[t] = acc;
    }
    __syncthreads();

    // ---- phase 2: 128 threads -> 2x16 coefficients ----
    if (t < 128) {
        const float4 a0 = sPart[t];
        const float4 a1 = sPart[t + 128];
        const float4 a2 = sPart[t + 256];
        const float4 a3 = sPart[t + 384];
        float4 m4;
        m4.x = a0.x + a1.x + a2.x + a3.x;
        m4.y = a0.y + a1.y + a2.y + a3.y;
        m4.z = a0.z + a1.z + a2.z + a3.z;
        m4.w = a0.w + a1.w + a2.w + a3.w;

        // quad within its own 16x16 patch: patch = colq>>2, col-in-patch = (colq&3)*4
        const int pb = row * 16 + (colq & 3) * 4;
        float part[NM];
        #pragma unroll
        for (int m = 0; m < NM; m++) {
            const float4 bq = __ldg(reinterpret_cast<const float4*>(bases + m * 256 + pb));
            part[m] = m4.x * bq.x + m4.y * bq.y + m4.z * bq.z + m4.w * bq.w;
        }
        // lane bit 2 selects the patch -> reduce over lane bits 0,1,3,4
        #pragma unroll
        for (int m = 0; m < NM; m++) {
            part[m] += __shfl_xor_sync(0xffffffffu, part[m], 1);
            part[m] += __shfl_xor_sync(0xffffffffu, part[m], 2);
            part[m] += __shfl_xor_sync(0xffffffffu, part[m], 8);
            part[m] += __shfl_xor_sync(0xffffffffu, part[m], 16);
        }
        const int lane = t & 31;
        if (lane == 0 || lane == 4) {
            const int w    = t >> 5;       // warp 0..3
            const int pidx = lane >> 2;    // patch 0/1
            #pragma unroll
            for (int m = 0; m < NM; m++) sW[w][pidx][m] = part[m];
        }
    }
    __syncthreads();
    if (t < 32) {
        const int m = t & 15, pidx = t >> 4;
        sCoef[pidx * NM + m] = (sW[0][pidx][m] + sW[1][pidx][m]
                              + sW[2][pidx][m] + sW[3][pidx][m]) * (1.0f / (float)CDIM);
    }
    __syncthreads();

    // ---- phase 3: 2048 float4 stores, full-line warp segments ----
    #pragma unroll
    for (int k = 0; k < 4; k++) {
        const int idx = t + k * 512;       // 0..2047
        const int m   = idx >> 7;          // base map
        const int gg  = idx & 127;
        const int rr  = gg >> 3;
        const int cq  = gg & 7;
        const float v = sCoef[(cq >> 2) * NM + m];
        float* o = out + ((size_t)(b * NM + m) * HDIM + (h0 + rr)) * WDIM
                       + (w0 + cq * 4);
        __stcs(reinterpret_cast<float4*>(o), make_float4(v, v, v, v));
    }
}

extern "C" void kernel_launch(void* const* d_in, const int* in_sizes, int n_in,
                              void* d_out, int out_size) {
    const float* x     = (const float*)d_in[0];
    const float* bases = (const float*)d_in[1];
    float*       out   = (float*)d_out;
    dim3 grid(WDIM / 32, HDIM / 16, 16);   // 7 x 14 x 16 = 1568 CTAs
    msp_dct_kernel<<<grid, 512>>>(x, bases, out);
}

// round 6
// speedup vs baseline: 1.0484x; 1.0484x over previous
#include <cuda_runtime.h>
#include <cuda_bf16.h>

#define PH    16
#define PW    16
#define NM    16
#define HDIM  224
#define WDIM  224
#define CDIM  64
#define HW    (HDIM * WDIM)
#define NPH   (HDIM / PH)    // 14
#define NPW   (WDIM / PW)    // 14

// coefficient scratch: [b][ph][pw][m]  (16*14*14*16 floats = 200 KB, L2-resident)
__device__ float g_coef[16 * NPH * NPW * NM];

// ================= Kernel A: pure-read coefficient computation =============
// One CTA per (b, ph, pw) patch, 256 threads (R3 geometry — best DRAM feed).
__global__ __launch_bounds__(256, 6)
void msp_dct_coef_kernel(const float* __restrict__ x,
                         const float* __restrict__ bases) {
    __shared__ float4 sPart[256];
    __shared__ float  sW[2][NM];

    const int t  = threadIdx.x;
    const int pw = blockIdx.x;
    const int ph = blockIdx.y;
    const int b  = blockIdx.z;
    const int h0 = ph * PH;
    const int w0 = pw * PW;

    const int g   = t & 63;
    const int pi  = g >> 2;
    const int pj4 = (g & 3) * 4;
    const int csl = t >> 6;
    {
        const float* p = x + ((size_t)(b * CDIM + csl * 16)) * HW
                           + (size_t)(h0 + pi) * WDIM + (w0 + pj4);
        float4 acc = make_float4(0.f, 0.f, 0.f, 0.f);
        #pragma unroll
        for (int cc = 0; cc < 16; cc++) {
            const float4 v = __ldcs(reinterpret_cast<const float4*>(p + (size_t)cc * HW));
            acc.x += v.x; acc.y += v.y; acc.z += v.z; acc.w += v.w;
        }
        sPart[t] = acc;
    }
    __syncthreads();

    if (t < 64) {
        const float4 a0 = sPart[t];
        const float4 a1 = sPart[t + 64];
        const float4 a2 = sPart[t + 128];
        const float4 a3 = sPart[t + 192];
        float4 m4;
        m4.x = a0.x + a1.x + a2.x + a3.x;
        m4.y = a0.y + a1.y + a2.y + a3.y;
        m4.z = a0.z + a1.z + a2.z + a3.z;
        m4.w = a0.w + a1.w + a2.w + a3.w;

        const int pb = pi * 16 + pj4;
        float part[NM];
        #pragma unroll
        for (int m = 0; m < NM; m++) {
            const float4 bq = __ldg(reinterpret_cast<const float4*>(bases + m * 256 + pb));
            part[m] = m4.x * bq.x + m4.y * bq.y + m4.z * bq.z + m4.w * bq.w;
        }
        #pragma unroll
        for (int m = 0; m < NM; m++) {
            #pragma unroll
            for (int off = 16; off; off >>= 1)
                part[m] += __shfl_xor_sync(0xffffffffu, part[m], off);
        }
        if ((t & 31) == 0) {
            const int w = t >> 5;
            #pragma unroll
            for (int m = 0; m < NM; m++) sW[w][m] = part[m];
        }
    }
    __syncthreads();
    if (t < NM) {
        // normal store -> stays in L2 for kernel B
        g_coef[(((b * NPH + ph) * NPW + pw) * NM) + t] =
            (sW[0][t] + sW[1][t]) * (1.0f / (float)CDIM);
    }
}

// ================= Kernel B: pure-write broadcast ===========================
// One CTA per (b, ph, pw) patch, 256 threads, 4 float4 streaming stores each.
__global__ __launch_bounds__(256, 8)
void msp_dct_bcast_kernel(float* __restrict__ out) {
    __shared__ float sCoef[NM];

    const int t  = threadIdx.x;
    const int pw = blockIdx.x;
    const int ph = blockIdx.y;
    const int b  = blockIdx.z;
    const int h0 = ph * PH;
    const int w0 = pw * PW;

    if (t < NM)
        sCoef[t] = g_coef[(((b * NPH + ph) * NPW + pw) * NM) + t];
    __syncthreads();

    #pragma unroll
    for (int k = 0; k < 4; k++) {
        const int idx = t + k * 256;        // 0..1023
        const int m   = idx >> 6;           // warp-uniform
        const int gg  = idx & 63;
        const int ii  = gg >> 2;
        const int jj  = (gg & 3) * 4;
        const float v = sCoef[m];
        float* o = out + ((size_t)(b * NM + m) * HDIM + (h0 + ii)) * WDIM
                       + (w0 + jj);
        __stcs(reinterpret_cast<float4*>(o), make_float4(v, v, v, v));
    }
}

extern "C" void kernel_launch(void* const* d_in, const int* in_sizes, int n_in,
                              void* d_out, int out_size) {
    const float* x     = (const float*)d_in[0];
    const float* bases = (const float*)d_in[1];
    float*       out   = (float*)d_out;
    dim3 grid(NPW, NPH, 16);                // 14 x 14 x 16 = 3136 CTAs
    msp_dct_coef_kernel<<<grid, 256>>>(x, bases);
    msp_dct_bcast_kernel<<<grid, 256>>>(out);
}